// round 11
// baseline (speedup 1.0000x reference)
#include <cuda_runtime.h>
#include <cuda_fp16.h>
#include <cstdint>
#include <cstring>

// Problem constants
#define BB 2
#define QQ 10
#define CC 64
#define HH 256
#define WW 256
#define HWXY (HH * WW)            // 65536
#define KK 9
#define LL 64800                  // 180*360
#define NN (QQ * HWXY)            // 655360 per-b
#define BQ (BB * QQ)              // 20

// fp16 channel-last scratch: row n holds 64 halfs (128B) = 8 uint4
__device__ uint4  g_xt16[(size_t)BQ * HWXY * 8];     // 167.8 MB
// per-n channel stats (mean, max) in fp32
__device__ float2 g_stats[(size_t)BQ * HWXY];        // 10.5 MB
// per-(b,l) record: [n0..n8, gatebits0..8, pad, pad]  (20 uints = 80B)
__device__ uint4  g_rec[(size_t)BB * LL * 5];        // 10.4 MB

__device__ __forceinline__ unsigned h2u(__half2 h) {
    unsigned u;
    memcpy(&u, &h, 4);
    return u;
}

// ---------------------------------------------------------------------------
// Kernel 1: smem-free transpose + stats.
// Thread (lane = hwq*8 + g) loads 8 channel rows (c = 8g..8g+7) x 4 hw
// (hw = warp_hw0 + 4*hwq .. +3) via 8x LDG.128, converts in registers to
// 4 output uint4 (one per n), writes fully coalesced 128B lines, and
// reduces stats over c via 3 shfl_xor within the 8 g-lanes.
// block 256 = 8 warps x 16 hw = 128 hw per block; grid (HW/128=512, 1, BQ)
// ---------------------------------------------------------------------------
__global__ void __launch_bounds__(256)
transpose_stats_kernel(const float* __restrict__ x,
                       uint4* __restrict__ xt,
                       float2* __restrict__ stats)
{
    const int tid  = threadIdx.x;
    const int warp = tid >> 5;
    const int lane = tid & 31;
    const int hwq  = lane >> 3;          // 0..3
    const int g    = lane & 7;           // 0..7  -> channels 8g..8g+7
    const int bq   = blockIdx.z;
    const int hw0  = blockIdx.x * 128 + warp * 16;   // warp's 16-hw slab
    const int hwb  = hw0 + hwq * 4;                  // this thread's 4 hw

    const size_t inbase = (size_t)bq * CC * HWXY;

    // 8 independent 16B loads (rows c=8g..8g+7), streaming: read-once data
    float4 v[8];
    #pragma unroll
    for (int i = 0; i < 8; i++)
        v[i] = __ldcs((const float4*)&x[inbase + (size_t)(8 * g + i) * HWXY + hwb]);

    // Pack + store: output n = hwb+j gets uint4 = halfs of c=8g..8g+7.
    // Lanes g=0..7 write consecutive uint4 -> full 128B lines per STG.
    const size_t outbase = ((size_t)bq * HWXY + hwb) * 8 + g;   // uint4 units
    {
        uint4 u;
        #define PACKJ(j, fld)                                             \
            u.x = h2u(__floats2half2_rn(v[0].fld, v[1].fld));             \
            u.y = h2u(__floats2half2_rn(v[2].fld, v[3].fld));             \
            u.z = h2u(__floats2half2_rn(v[4].fld, v[5].fld));             \
            u.w = h2u(__floats2half2_rn(v[6].fld, v[7].fld));             \
            xt[outbase + (size_t)(j) * 8] = u;
        PACKJ(0, x)
        PACKJ(1, y)
        PACKJ(2, z)
        PACKJ(3, w)
        #undef PACKJ
    }

    // Stats: partial sum/max over this thread's 8 c's for each of 4 hw,
    // then butterfly across the 8 g-lanes (consecutive lanes, xor 1/2/4).
    float s0 = v[0].x, m0 = v[0].x;
    float s1 = v[0].y, m1 = v[0].y;
    float s2 = v[0].z, m2 = v[0].z;
    float s3 = v[0].w, m3 = v[0].w;
    #pragma unroll
    for (int i = 1; i < 8; i++) {
        s0 += v[i].x;  m0 = fmaxf(m0, v[i].x);
        s1 += v[i].y;  m1 = fmaxf(m1, v[i].y);
        s2 += v[i].z;  m2 = fmaxf(m2, v[i].z);
        s3 += v[i].w;  m3 = fmaxf(m3, v[i].w);
    }
    #pragma unroll
    for (int o = 1; o < 8; o <<= 1) {
        s0 += __shfl_xor_sync(0xffffffffu, s0, o);
        m0  = fmaxf(m0, __shfl_xor_sync(0xffffffffu, m0, o));
        s1 += __shfl_xor_sync(0xffffffffu, s1, o);
        m1  = fmaxf(m1, __shfl_xor_sync(0xffffffffu, m1, o));
        s2 += __shfl_xor_sync(0xffffffffu, s2, o);
        m2  = fmaxf(m2, __shfl_xor_sync(0xffffffffu, m2, o));
        s3 += __shfl_xor_sync(0xffffffffu, s3, o);
        m3  = fmaxf(m3, __shfl_xor_sync(0xffffffffu, m3, o));
    }
    // lanes with g<4 write stats for j=g: warp covers 16 consecutive n (128B)
    if (g < 4) {
        float ss, mm;
        if      (g == 0) { ss = s0; mm = m0; }
        else if (g == 1) { ss = s1; mm = m1; }
        else if (g == 2) { ss = s2; mm = m2; }
        else             { ss = s3; mm = m3; }
        stats[(size_t)bq * HWXY + hwb + g] = make_float2(ss * (1.0f / 64.0f), mm);
    }
}

// ---------------------------------------------------------------------------
// Kernel 2: gate precompute. One thread per (b,l): read idx + stats, compute
// all 9 (1+sigmoid) gates, write packed record [n0..8, gate0..8, pad2].
// grid ((BB*LL+255)/256), block 256
// ---------------------------------------------------------------------------
__global__ void __launch_bounds__(256)
gate_kernel(const float2* __restrict__ stats,
            const void* __restrict__ idx_raw,   // (64800,9) int32 OR int64
            const float* __restrict__ att_w,    // (9,2,9)
            const float* __restrict__ att_b,    // (9,)
            unsigned* __restrict__ rec)         // (BB*LL, 20) uints
{
    __shared__ float s_aw[KK * 2 * KK];
    __shared__ float s_ab[KK];
    const int tid = threadIdx.x;
    if (tid < KK * 2 * KK) s_aw[tid] = att_w[tid];
    if (tid < KK)          s_ab[tid] = att_b[tid];
    __syncthreads();

    const int gid = blockIdx.x * 256 + tid;
    if (gid >= BB * LL) return;
    const int b = gid / LL;
    const int l = gid - b * LL;

    // dtype sniff: int64 values < 2^31 have zero high words at odd 32-bit slots
    const int* __restrict__ i32 = (const int*)idx_raw;
    const bool is64 = (i32[1] | i32[3] | i32[5] | i32[7] |
                       i32[9] | i32[11] | i32[13] | i32[15]) == 0;

    int n[KK];
    #pragma unroll
    for (int k = 0; k < KK; k++) {
        const size_t pos = (size_t)l * KK + k;
        n[k] = is64 ? (int)((const long long*)idx_raw)[pos] : i32[pos];
    }

    float mn[KK], mx[KK];
    #pragma unroll
    for (int k = 0; k < KK; k++) {
        const float2 st = __ldg(&stats[(size_t)b * NN + n[k]]);
        mn[k] = st.x;
        mx[k] = st.y;
    }

    unsigned r[20];
    #pragma unroll
    for (int k = 0; k < KK; k++) r[k] = (unsigned)n[k];
    #pragma unroll
    for (int i = 0; i < KK; i++) {
        float z = s_ab[i];
        #pragma unroll
        for (int k = 0; k < KK; k++) {
            z = fmaf(mn[k], s_aw[i * 18 + k],     z);
            z = fmaf(mx[k], s_aw[i * 18 + 9 + k], z);
        }
        const float gte = 1.0f + 1.0f / (1.0f + __expf(-z));
        r[KK + i] = __float_as_uint(gte);
    }
    r[18] = 0; r[19] = 0;

    uint4* __restrict__ rec4 = (uint4*)rec;
    const size_t base = (size_t)gid * 5;
    #pragma unroll
    for (int q = 0; q < 5; q++)
        rec4[base + q] = make_uint4(r[q*4], r[q*4+1], r[q*4+2], r[q*4+3]);
}

// ---------------------------------------------------------------------------
// Kernel 3: gather + contraction only. Per l: one record load + 18 shfl +
// 9 gather LDG + 18 FMA. block 256 = 8 warps x 4 l = 32 consecutive l.
// grid: (LL/32 = 2025, BB)
// ---------------------------------------------------------------------------
__global__ void __launch_bounds__(256)
fused_kernel(const uint* __restrict__ xt16,      // half2 view of scratch
             const unsigned* __restrict__ rec,   // (BB*LL, 20)
             const float* __restrict__ tc_w,     // (64,9)
             const float* __restrict__ tc_b,     // (64,)
             float* __restrict__ out)            // (B, 64, L)
{
    __shared__ __align__(16) float s_out[CC][36];

    const int tid  = threadIdx.x;
    const int warp = tid >> 5;
    const int lane = tid & 31;
    const int b    = blockIdx.y;
    const int lblk = blockIdx.x * 32;
    const int c0   = lane * 2;

    float w0[KK], w1[KK];
    #pragma unroll
    for (int k = 0; k < KK; k++) {
        w0[k] = __ldg(&tc_w[c0 * KK + k]);
        w1[k] = __ldg(&tc_w[(c0 + 1) * KK + k]);
    }
    const float bias0 = __ldg(&tc_b[c0]);
    const float bias1 = __ldg(&tc_b[c0 + 1]);

    #pragma unroll
    for (int j = 0; j < 4; j++) {
        const int l  = lblk + warp * 4 + j;
        const int ll = warp * 4 + j;

        // one 72B record read: lanes 0..8 -> n, lanes 9..17 -> gate
        unsigned r = 0;
        if (lane < 18) r = rec[((size_t)b * LL + l) * 20 + lane];

        // broadcast indices, issue all gathers immediately (stay in flight)
        int n[KK];
        #pragma unroll
        for (int k = 0; k < KK; k++)
            n[k] = (int)__shfl_sync(0xffffffffu, r, k);

        uint vu[KK];
        #pragma unroll
        for (int k = 0; k < KK; k++)
            vu[k] = xt16[((size_t)b * NN + (size_t)n[k]) * 32 + lane];

        float o0 = bias0, o1 = bias1;
        #pragma unroll
        for (int k = 0; k < KK; k++) {
            const float sc = __uint_as_float(__shfl_sync(0xffffffffu, r, KK + k));
            const float2 v = __half22float2(*(const __half2*)&vu[k]);
            o0 = fmaf(v.x * sc, w0[k], o0);
            o1 = fmaf(v.y * sc, w1[k], o1);
        }

        s_out[c0][ll]     = o0;
        s_out[c0 + 1][ll] = o1;
    }
    __syncthreads();

    // Coalesced output: 64 rows x 8 float4, full 128B lines
    #pragma unroll
    for (int s = tid; s < 512; s += 256) {
        const int c = s >> 3;
        const int q = s & 7;
        const float4 vv = *(const float4*)&s_out[c][q * 4];
        *(float4*)&out[((size_t)(b * CC + c)) * LL + lblk + q * 4] = vv;
    }
}

// ---------------------------------------------------------------------------
extern "C" void kernel_launch(void* const* d_in, const int* in_sizes, int n_in,
                              void* d_out, int out_size)
{
    const float* x     = (const float*)d_in[0];      // (20, 64, 256, 256)
    const void*  idx   = d_in[1];                    // (64800, 9) int32 or int64
    const float* att_w = (const float*)d_in[2];      // (9,2,9)
    const float* att_b = (const float*)d_in[3];      // (9,)
    const float* tc_w  = (const float*)d_in[4];      // (64,9)
    const float* tc_b  = (const float*)d_in[5];      // (64,)
    float*       out   = (float*)d_out;              // (2, 64, 180, 360)

    uint4* xt;  float2* stats;  uint4* rec;
    cudaGetSymbolAddress((void**)&xt, g_xt16);
    cudaGetSymbolAddress((void**)&stats, g_stats);
    cudaGetSymbolAddress((void**)&rec, g_rec);

    {
        dim3 grid(HWXY / 128, 1, BQ);
        transpose_stats_kernel<<<grid, 256>>>(x, xt, stats);
    }
    {
        dim3 grid((BB * LL + 255) / 256);
        gate_kernel<<<grid, 256>>>(stats, idx, att_w, att_b, (unsigned*)rec);
    }
    {
        dim3 grid(LL / 32, BB);
        fused_kernel<<<grid, 256>>>((const uint*)xt, (const unsigned*)rec,
                                    tc_w, tc_b, out);
    }
}